// round 4
// baseline (speedup 1.0000x reference)
#include <cuda_runtime.h>

#define NN 100000
#define NE 3200000
#define F  64

// Scratch (no allocations allowed)
__device__ __align__(16) int   g_cnt[NN];        // in-degree counts
__device__ __align__(16) int   g_off[NN + 1];    // CSR offsets
__device__ __align__(16) int   g_cur[NN];        // fill cursors
__device__ __align__(16) int   g_srcs[NE];       // CSR src list (by dst)
__device__ __align__(16) float g_dis[NN];        // d^-1/2
__device__ __align__(16) float g_xs[NN * 2];     // x * dis
__device__ __align__(16) float g_agg2[NN * 2];   // layer-1 aggregation (complete)
__device__ __align__(16) float g_h1s[NN * F];    // relu(layer1) * dis
__device__ __align__(16) float g_agg64[NN * F];  // layer-2 aggregation (complete)
__device__ float g_red;
__device__ int   g_is64;

__device__ __forceinline__ int load_idx(const void* ei, long long e, int is64) {
    if (is64) return (int)((const long long*)ei)[e];
    return ((const int*)ei)[e];
}

// 0. dtype detection (int64 vs int32 edge_index)
__global__ void k_detect(const long long* __restrict__ ei) {
    int is64 = 1;
    for (int i = 0; i < 64; i++) {
        long long v = ei[i];
        if (v < 0 || v >= NN) { is64 = 0; break; }
    }
    g_is64 = is64;
}

// 1. zero counters
__global__ void k_zero() {
    int i = blockIdx.x * blockDim.x + threadIdx.x;
    if (i < NN) {
        g_cnt[i] = 0;
        if (i == 0) g_red = 0.0f;
    }
}

// 2. in-degree count
__global__ void k_deg(const void* __restrict__ ei) {
    int e = blockIdx.x * blockDim.x + threadIdx.x;
    if (e >= NE) return;
    int d = load_idx(ei, (long long)NE + e, g_is64);
    atomicAdd(&g_cnt[d], 1);
}

// 3. single-block exclusive scan + dis computation
__global__ void k_scan() {
    __shared__ int ssum[1024];
    const int CH = (NN + 1023) / 1024;      // 98
    int t = threadIdx.x;
    int beg = t * CH;
    int end = min(beg + CH, NN);

    int s = 0;
    for (int i = beg; i < end; i++) s += g_cnt[i];
    ssum[t] = s;
    __syncthreads();
    // Hillis-Steele inclusive scan
    for (int o = 1; o < 1024; o <<= 1) {
        int u = (t >= o) ? ssum[t - o] : 0;
        __syncthreads();
        ssum[t] += u;
        __syncthreads();
    }
    int off = ssum[t] - s;                   // exclusive base
    for (int i = beg; i < end; i++) {
        g_off[i] = off;
        g_cur[i] = off;
        int c = g_cnt[i];
        g_dis[i] = rsqrtf((float)(c + 1));   // +1 self loop
        off += c;
    }
    if (t == 1023) g_off[NN] = off;          // == NE
}

// 4. CSR fill
__global__ void k_fill(const void* __restrict__ ei) {
    int e = blockIdx.x * blockDim.x + threadIdx.x;
    if (e >= NE) return;
    int is64 = g_is64;
    int s = load_idx(ei, e, is64);
    int d = load_idx(ei, (long long)NE + e, is64);
    int slot = atomicAdd(&g_cur[d], 1);
    g_srcs[slot] = s;
}

// 5. pre-scaled input features: xs = x * dis
__global__ void k_prep_x(const float* __restrict__ x) {
    int i = blockIdx.x * blockDim.x + threadIdx.x;
    if (i >= NN) return;
    float di = g_dis[i];
    float2 v = reinterpret_cast<const float2*>(x)[i];
    reinterpret_cast<float2*>(g_xs)[i] = make_float2(v.x * di, v.y * di);
}

// 6. layer-1 gather: warp per node, lanes across edges, warp-reduce float2
__global__ void k_gather2() {
    int w = (blockIdx.x * blockDim.x + threadIdx.x) >> 5;
    int lane = threadIdx.x & 31;
    if (w >= NN) return;
    int beg = g_off[w], end = g_off[w + 1];
    float ax = 0.0f, ay = 0.0f;
    for (int e = beg + lane; e < end; e += 32) {
        int s = g_srcs[e];
        float2 v = reinterpret_cast<const float2*>(g_xs)[s];
        ax += v.x; ay += v.y;
    }
    #pragma unroll
    for (int o = 16; o; o >>= 1) {
        ax += __shfl_xor_sync(0xffffffffu, ax, o);
        ay += __shfl_xor_sync(0xffffffffu, ay, o);
    }
    if (lane == 0) {
        float di = g_dis[w];
        float2 self = reinterpret_cast<const float2*>(g_xs)[w];
        reinterpret_cast<float2*>(g_agg2)[w] =
            make_float2(di * (ax + self.x), di * (ay + self.y));
    }
}

// 7. layer-1 dense: h1s = relu(agg2 @ W1 + b1) * dis
__global__ void k_layer1(const float* __restrict__ W1,
                         const float* __restrict__ b1) {
    int idx = blockIdx.x * blockDim.x + threadIdx.x;
    if (idx >= NN * F) return;
    int i = idx >> 6, c = idx & 63;
    float a0 = g_agg2[2 * i], a1 = g_agg2[2 * i + 1];
    float v = fmaf(a0, W1[c], fmaf(a1, W1[64 + c], b1[c]));
    g_h1s[idx] = fmaxf(v, 0.0f) * g_dis[i];
}

// 8. layer-2 gather: warp per node; lane owns 2 features (float2);
//    4-edge unroll for MLP. agg64[d] = dis[d]*(sum h1s[src] + h1s[d])
__global__ void k_gather64() {
    int w = (blockIdx.x * blockDim.x + threadIdx.x) >> 5;
    int lane = threadIdx.x & 31;
    if (w >= NN) return;
    int beg = g_off[w], end = g_off[w + 1];
    const float2* h = reinterpret_cast<const float2*>(g_h1s);

    float2 acc = h[w * 32 + lane];           // self-loop term
    int e = beg;
    for (; e + 4 <= end; e += 4) {
        int s0 = g_srcs[e], s1 = g_srcs[e + 1];
        int s2 = g_srcs[e + 2], s3 = g_srcs[e + 3];
        float2 v0 = h[s0 * 32 + lane];
        float2 v1 = h[s1 * 32 + lane];
        float2 v2 = h[s2 * 32 + lane];
        float2 v3 = h[s3 * 32 + lane];
        acc.x += v0.x + v1.x + v2.x + v3.x;
        acc.y += v0.y + v1.y + v2.y + v3.y;
    }
    for (; e < end; e++) {
        int s = g_srcs[e];
        float2 v = h[s * 32 + lane];
        acc.x += v.x; acc.y += v.y;
    }
    float di = g_dis[w];
    reinterpret_cast<float2*>(g_agg64)[w * 32 + lane] =
        make_float2(di * acc.x, di * acc.y);
}

// 9. fused layer-2 dense + ReLU + mean-pool dot with Wl
__global__ void k_layer2_reduce(const float* __restrict__ W2,
                                const float* __restrict__ b2,
                                const float* __restrict__ Wl) {
    __shared__ float sW[64 * 64];
    __shared__ float sh[4][64];
    __shared__ float sred[8];

    int t = threadIdx.x;
    for (int j = t; j < 4096; j += 256) sW[j] = W2[j];

    int r = t >> 6, c = t & 63;
    float bc  = b2[c];
    float wlc = Wl[c];
    int base = blockIdx.x * 32;

    float partial = 0.0f;
    for (int g = 0; g < 8; g++) {
        int i = base + g * 4 + r;            // NN % 32 == 0
        __syncthreads();
        sh[r][c] = g_agg64[i * 64 + c];
        __syncthreads();
        float m = bc;
        #pragma unroll
        for (int k = 0; k < 64; k++) m = fmaf(sh[r][k], sW[k * 64 + c], m);
        partial += fmaxf(m, 0.0f) * wlc;
    }

    #pragma unroll
    for (int o = 16; o; o >>= 1) partial += __shfl_down_sync(0xffffffffu, partial, o);
    if ((t & 31) == 0) sred[t >> 5] = partial;
    __syncthreads();
    if (t < 8) {
        float v = sred[t];
        #pragma unroll
        for (int o = 4; o; o >>= 1) v += __shfl_down_sync(0xffu, v, o);
        if (t == 0) atomicAdd(&g_red, v);
    }
}

// 10. final scalar
__global__ void k_final(const float* __restrict__ bl, float* __restrict__ out) {
    out[0] = g_red * (1.0f / NN) + bl[0];
}

extern "C" void kernel_launch(void* const* d_in, const int* in_sizes, int n_in,
                              void* d_out, int out_size) {
    const float* x  = (const float*)d_in[0];
    const void*  ei = d_in[1];
    const float* W1 = (const float*)d_in[2];
    const float* b1 = (const float*)d_in[3];
    const float* W2 = (const float*)d_in[4];
    const float* b2 = (const float*)d_in[5];
    const float* Wl = (const float*)d_in[6];
    const float* bl = (const float*)d_in[7];
    float* out = (float*)d_out;

    k_detect<<<1, 1>>>((const long long*)ei);
    k_zero<<<(NN + 255) / 256, 256>>>();
    k_deg<<<(NE + 255) / 256, 256>>>(ei);
    k_scan<<<1, 1024>>>();
    k_fill<<<(NE + 255) / 256, 256>>>(ei);
    k_prep_x<<<(NN + 255) / 256, 256>>>(x);
    k_gather2<<<(NN * 32 + 255) / 256, 256>>>();
    k_layer1<<<(NN * F + 255) / 256, 256>>>(W1, b1);
    k_gather64<<<(NN * 32 + 255) / 256, 256>>>();
    k_layer2_reduce<<<NN / 32, 256>>>(W2, b2, Wl);
    k_final<<<1, 1>>>(bl, out);
}